// round 11
// baseline (speedup 1.0000x reference)
#include <cuda_runtime.h>

// QnnFormerVQC round 11: SINGLE kernel, spill-free block-0 prep.
//  - Block 0 builds the fixed 16x16 circuit unitary W by evolving the 16
//    basis states DIRECTLY IN SHARED MEMORY (Wsh doubles as the psi storage;
//    layout [amplitude][column] == W[i][j]; no register spills in the prep
//    branch), stores it to g_W, release-publishes via g_flag.
//  - Other blocks: encode first (W-independent), then thread-0 nanosleep-spin
//    on g_flag, copy g_W -> Wsh, run psi = W @ p + measurement.
//  - Self-resetting (last block zeroes flag/counter): deterministic per call.
// Circuit reductions (verified vs round-3 literal oracle):
//  - whole 3-layer shared-parameter circuit == one 16x16 unitary W
//    (RX(beta0/1) folded into next layer's U; reference's _apmcx == swap
//    of amplitudes 7<->15; diffuser == psi_i -= sum(9,11,13,15)/2 on that set;
//    CX-RZ-CX chain == diagonal phases).
//  - RX(beta2) folded into measurement: z'=cb*z+sb*y, y'=cb*y-sb*z, x'=x.
//  - T = sum|psi|^2 == 1 (unitarity) -> z = 1 - 2*s1.
// Bit convention: qubit q <-> mask (8 >> q), qubit 0 = MSB.

#define NQ 4
#define NL 3

__device__ float2 g_W[16][16];   // W[i][j] = <i| circuit |j>
__device__ float2 g_mb;          // (cos(beta2), sin(beta2)), FULL angle
__device__ int    g_flag = 0;    // W published?
__device__ int    g_done = 0;    // finished blocks (self-reset)

__device__ __forceinline__ float2 cmulh(float2 a, float2 b) {
    return make_float2(a.x * b.x - a.y * b.y, a.x * b.y + a.y * b.x);
}
__device__ __forceinline__ float2 caddh(float2 a, float2 b) {
    return make_float2(a.x + b.x, a.y + b.y);
}

struct PS {
    float2 U[NL][NQ][2][2];
    float  ce[NL][NQ], se[NL][NQ];
    float2 dg[NL][16];
};

// encoding tensor p (real) from one float4 of inputs
__device__ __forceinline__ void encode(float4 xv, float* p) {
    float cq[4], sq[4];
    __sincosf(0.5f * xv.x, &sq[0], &cq[0]);
    __sincosf(0.5f * xv.y, &sq[1], &cq[1]);
    __sincosf(0.5f * xv.z, &sq[2], &cq[2]);
    __sincosf(0.5f * xv.w, &sq[3], &cq[3]);
    float a01[4], a012[8];
    a01[0] = cq[0] * cq[1]; a01[1] = cq[0] * sq[1];
    a01[2] = sq[0] * cq[1]; a01[3] = sq[0] * sq[1];
    #pragma unroll
    for (int k = 0; k < 4; k++) {
        a012[2 * k]     = a01[k] * cq[2];
        a012[2 * k + 1] = a01[k] * sq[2];
    }
    #pragma unroll
    for (int m = 0; m < 8; m++) {
        p[2 * m]     = a012[m] * cq[3];
        p[2 * m + 1] = a012[m] * sq[3];
    }
}

__global__ void __launch_bounds__(256)
vqc_kernel(const float4* __restrict__ x,
           float* __restrict__ out,
           const float* __restrict__ w,
           const float* __restrict__ ew,
           const float* __restrict__ gam,
           const float* __restrict__ bet,
           int n) {
    __shared__ PS ps;                 // block 0 only
    __shared__ float2 Wsh[16][16];    // block 0: evolution storage == W
    __shared__ float2 mbsh;

    int t = threadIdx.x;
    int b = blockIdx.x * blockDim.x + t;
    bool act = (b < n);

    // ---- W-independent phase ----
    float p[16];
    if (act) encode(x[b], p);

    if (blockIdx.x == 0) {
        // ---- parameter tables ----
        if (t < NL * NQ) {
            int L = t / NQ, q = t % NQ;
            float th = w[L * NQ + q];
            float c, s;
            __sincosf(0.5f * th, &s, &c);
            float2 RX[2][2] = {{{c, 0.f}, {0.f, -s}}, {{0.f, -s}, {c, 0.f}}};
            float2 RY[2][2] = {{{c, 0.f}, {-s, 0.f}}, {{s, 0.f}, {c, 0.f}}};
            float2 RZ[2][2] = {{{c, -s}, {0.f, 0.f}}, {{0.f, 0.f}, {c, s}}};
            float2 T[2][2], M[2][2];
            #pragma unroll
            for (int i = 0; i < 2; i++)
                #pragma unroll
                for (int j = 0; j < 2; j++)
                    T[i][j] = caddh(cmulh(RY[i][0], RX[0][j]),
                                    cmulh(RY[i][1], RX[1][j]));
            #pragma unroll
            for (int i = 0; i < 2; i++)
                #pragma unroll
                for (int j = 0; j < 2; j++)
                    M[i][j] = caddh(cmulh(RZ[i][0], T[0][j]),
                                    cmulh(RZ[i][1], T[1][j]));
            if (L > 0) {  // fold previous layer's RX(beta): M_eff = M * RXb
                float cb, sb;
                __sincosf(0.5f * bet[L - 1], &sb, &cb);
                float2 RXb[2][2] = {{{cb, 0.f}, {0.f, -sb}},
                                    {{0.f, -sb}, {cb, 0.f}}};
                float2 E[2][2];
                #pragma unroll
                for (int i = 0; i < 2; i++)
                    #pragma unroll
                    for (int j = 0; j < 2; j++)
                        E[i][j] = caddh(cmulh(M[i][0], RXb[0][j]),
                                        cmulh(M[i][1], RXb[1][j]));
                #pragma unroll
                for (int i = 0; i < 2; i++)
                    #pragma unroll
                    for (int j = 0; j < 2; j++)
                        M[i][j] = E[i][j];
            }
            #pragma unroll
            for (int i = 0; i < 2; i++)
                #pragma unroll
                for (int j = 0; j < 2; j++)
                    ps.U[L][q][i][j] = M[i][j];
            __sincosf(0.5f * ew[L * NQ + q], &ps.se[L][q], &ps.ce[L][q]);
        }
        if (t >= 16 && t < 16 + NL * 16) {
            int r = t - 16;
            int L = r / 16, idx = r % 16;
            int k = 0;
            #pragma unroll
            for (int i = 0; i < 3; i++) {
                int bi = (idx >> (3 - i)) & 1;
                int bj = (idx >> (2 - i)) & 1;
                if (bi == bj) k++;
            }
            float ang = 0.5f * gam[L] * (float)(3 - 2 * k);
            float sa, ca;
            __sincosf(ang, &sa, &ca);
            ps.dg[L][idx] = make_float2(ca, sa);
        }
        if (t == 64) {
            float cb, sb;
            __sincosf(bet[NL - 1], &sb, &cb);  // FULL angle
            float2 m2 = make_float2(cb, sb);
            g_mb = m2;
            mbsh = m2;
        }
        __syncthreads();

        // ---- basis evolution in SHARED (thread t<16 owns column t) ----
        if (t < 16) {
            #pragma unroll
            for (int i = 0; i < 16; i++)
                Wsh[i][t] = make_float2(i == t ? 1.f : 0.f, 0.f);

            #pragma unroll
            for (int L = 0; L < NL; L++) {
                #pragma unroll
                for (int q = 0; q < NQ; q++) {
                    float2 u00 = ps.U[L][q][0][0], u01 = ps.U[L][q][0][1];
                    float2 u10 = ps.U[L][q][1][0], u11 = ps.U[L][q][1][1];
                    int mask = 8 >> q;
                    #pragma unroll
                    for (int i = 0; i < 16; i++) {
                        if (i & mask) continue;
                        int j = i | mask;
                        float2 a = Wsh[i][t], d = Wsh[j][t];
                        float nr, ni, mr, mi;
                        nr = u00.x * a.x; nr = fmaf(-u00.y, a.y, nr);
                        nr = fmaf(u01.x, d.x, nr); nr = fmaf(-u01.y, d.y, nr);
                        ni = u00.x * a.y; ni = fmaf(u00.y, a.x, ni);
                        ni = fmaf(u01.x, d.y, ni); ni = fmaf(u01.y, d.x, ni);
                        mr = u10.x * a.x; mr = fmaf(-u10.y, a.y, mr);
                        mr = fmaf(u11.x, d.x, mr); mr = fmaf(-u11.y, d.y, mr);
                        mi = u10.x * a.y; mi = fmaf(u10.y, a.x, mi);
                        mi = fmaf(u11.x, d.y, mi); mi = fmaf(u11.y, d.x, mi);
                        Wsh[i][t] = make_float2(nr, ni);
                        Wsh[j][t] = make_float2(mr, mi);
                    }
                }
                #pragma unroll
                for (int q = 0; q < NQ; q++) {
                    float c = ps.ce[L][q], s = ps.se[L][q];
                    int cmask = 8 >> q;
                    int tmask = 8 >> ((q + 1) & 3);
                    #pragma unroll
                    for (int i = 0; i < 16; i++) {
                        if (!(i & cmask) || (i & tmask)) continue;
                        int j = i | tmask;
                        float2 a = Wsh[i][t], d = Wsh[j][t];
                        Wsh[i][t] = make_float2(fmaf(c, a.x,  s * d.y),
                                                fmaf(c, a.y, -s * d.x));
                        Wsh[j][t] = make_float2(fmaf(s, a.y,  c * d.x),
                                                fmaf(-s, a.x, c * d.y));
                    }
                }
                {   // diffuser: psi_i -= (psi9+psi11+psi13+psi15)/2
                    float2 a9 = Wsh[9][t], a11 = Wsh[11][t];
                    float2 a13 = Wsh[13][t], a15 = Wsh[15][t];
                    float sr = (a9.x + a11.x) + (a13.x + a15.x);
                    float si = (a9.y + a11.y) + (a13.y + a15.y);
                    sr *= 0.5f; si *= 0.5f;
                    Wsh[9][t]  = make_float2(a9.x - sr,  a9.y - si);
                    Wsh[11][t] = make_float2(a11.x - sr, a11.y - si);
                    Wsh[13][t] = make_float2(a13.x - sr, a13.y - si);
                    Wsh[15][t] = make_float2(a15.x - sr, a15.y - si);
                }
                #pragma unroll
                for (int i = 0; i < 16; i++) {  // RZZ diagonal
                    float2 ph = ps.dg[L][i];
                    float2 a = Wsh[i][t];
                    Wsh[i][t] = make_float2(fmaf(ph.x, a.x, -ph.y * a.y),
                                            fmaf(ph.x, a.y,  ph.y * a.x));
                }
            }
            #pragma unroll
            for (int i = 0; i < 16; i++) g_W[i][t] = Wsh[i][t];
        }
        __syncthreads();
        if (t == 0) {
            __threadfence();           // publish g_W / g_mb
            atomicExch(&g_flag, 1);    // release
        }
        // Wsh already holds W for block 0
    } else {
        if (t == 0) {
            while (*(volatile int*)&g_flag == 0) { __nanosleep(64); }
            __threadfence();           // acquire
        }
        __syncthreads();
        if (t < 128) {
            reinterpret_cast<float4*>(&Wsh[0][0])[t] =
                reinterpret_cast<const float4*>(&g_W[0][0])[t];
        }
        if (t == 128) mbsh = g_mb;
    }
    __syncthreads();

    if (act) {
        // ---- psi = W @ p (complex x real matvec, 512 FMA) ----
        float2 psi[16];
        #pragma unroll
        for (int i = 0; i < 16; i++) {
            const float4* row = reinterpret_cast<const float4*>(&Wsh[i][0]);
            float re = 0.f, im = 0.f;
            #pragma unroll
            for (int jj = 0; jj < 8; jj++) {
                float4 v = row[jj];  // (W[i][2jj].re,.im, W[i][2jj+1].re,.im)
                re = fmaf(v.x, p[2 * jj], re);
                im = fmaf(v.y, p[2 * jj], im);
                re = fmaf(v.z, p[2 * jj + 1], re);
                im = fmaf(v.w, p[2 * jj + 1], im);
            }
            psi[i] = make_float2(re, im);
        }

        // ---- measurement with RX(beta2) fold; T == 1 by unitarity ----
        float cb = mbsh.x, sb = mbsh.y;

        float sq2[16];
        #pragma unroll
        for (int i = 0; i < 16; i++)
            sq2[i] = fmaf(psi[i].x, psi[i].x, psi[i].y * psi[i].y);

        float res[12];
        #pragma unroll
        for (int q = 0; q < NQ; q++) {
            int mask = 8 >> q;
            float s1 = 0.f;
            #pragma unroll
            for (int i = 0; i < 16; i++)
                if (i & mask) s1 += sq2[i];
            float z = fmaf(-2.f, s1, 1.f);

            float xr = 0.f, yi = 0.f;
            #pragma unroll
            for (int i = 0; i < 16; i++) {
                if (i & mask) continue;
                int j = i | mask;
                float2 a = psi[i], d = psi[j];
                xr = fmaf(a.x, d.x, xr); xr = fmaf(a.y, d.y, xr);
                yi = fmaf(a.x, d.y, yi); yi = fmaf(-a.y, d.x, yi);
            }
            float xo = 2.f * xr, yo = 2.f * yi;
            res[q]     = fmaf(cb, z, sb * yo);      // z' = cb*z + sb*y
            res[4 + q] = xo;                        // x' = x
            res[8 + q] = fmaf(cb, yo, -sb * z);     // y' = cb*y - sb*z
        }

        float4* o = reinterpret_cast<float4*>(out + (size_t)b * 12);
        o[0] = make_float4(res[0], res[1], res[2],  res[3]);
        o[1] = make_float4(res[4], res[5], res[6],  res[7]);
        o[2] = make_float4(res[8], res[9], res[10], res[11]);
    }

    // ---- self-reset: every call starts and ends with flag == 0 ----
    if (t == 0) {
        int v = atomicAdd(&g_done, 1);
        if (v == (int)gridDim.x - 1) {   // last block
            g_done = 0;
            __threadfence();
            atomicExch(&g_flag, 0);
        }
    }
}

extern "C" void kernel_launch(void* const* d_in, const int* in_sizes, int n_in,
                              void* d_out, int out_size) {
    const float* x   = (const float*)d_in[0];  // (B, 4)
    const float* w   = (const float*)d_in[1];  // (3, 4)
    const float* ew  = (const float*)d_in[2];  // (3, 4)
    const float* gam = (const float*)d_in[3];  // (3,)
    const float* bet = (const float*)d_in[4];  // (3,)
    float* out = (float*)d_out;                // (B, 12)

    int n = in_sizes[0] / 4;

    int threads = 256;
    int blocks = (n + threads - 1) / threads;
    vqc_kernel<<<blocks, threads>>>((const float4*)x, out, w, ew, gam, bet, n);
}

// round 13
// speedup vs baseline: 1.0860x; 1.0860x over previous
#include <cuda_runtime.h>

// QnnFormerVQC round 13: SINGLE kernel, per-block redundant W build via
// warp-shuffle butterflies (no cross-block sync, no register bloat).
//  - Every block: 128 threads compute the small parameter tables into shared
//    (__sincosf), then ALL 8 warps evolve the 16 basis states: one amplitude
//    per lane (i = lane&15), column = 2*warp + lane/16; gate pairs exchange
//    via __shfl_xor_sync. ~60 shfl + ~300 FMA per block, ~0.9us, all warps
//    busy -> no bubble. Result -> Wsh[16][16] in shared.
//  - Then the verified matvec body: psi = W @ p (512 FMA) + measurement with
//    RX(beta2) folded in (z'=cb*z+sb*y, y'=cb*y-sb*z, x'=x; T==1 unitarity).
// Circuit reductions (verified vs round-3 literal oracle):
//  - RZ*RY*RX(w) -> one 2x2 matrix U per (L,q); RX(beta0/1) folded into the
//    next layer's U.  - reference's _apmcx == swap amplitudes 7<->15, so the
//    H/X/MCX block == psi_i -= sum(psi9,11,13,15)/2 on {9,11,13,15}.
//  - CX-RZ(gamma)-CX chain == 16-entry diagonal phase table.
// Bit convention: qubit q <-> mask (8 >> q), qubit 0 = MSB.

#define NQ 4
#define NL 3

struct PS {
    float2 U[NL][NQ][2][2];
    float  ce[NL][NQ], se[NL][NQ];
    float2 dg[NL][16];
};

__device__ __forceinline__ float2 cmulh(float2 a, float2 b) {
    return make_float2(a.x * b.x - a.y * b.y, a.x * b.y + a.y * b.x);
}
__device__ __forceinline__ float2 caddh(float2 a, float2 b) {
    return make_float2(a.x + b.x, a.y + b.y);
}

__global__ void __launch_bounds__(256)
vqc_kernel(const float4* __restrict__ x,
           float* __restrict__ out,
           const float* __restrict__ w,
           const float* __restrict__ ew,
           const float* __restrict__ gam,
           const float* __restrict__ bet,
           int n) {
    __shared__ PS ps;
    __shared__ float2 Wsh[16][16];
    __shared__ float2 mbsh;

    int t = threadIdx.x;
    int b = blockIdx.x * blockDim.x + t;
    bool act = (b < n);

    // issue the input load early (latency hidden behind table + evolution)
    float4 xv = act ? x[b] : make_float4(0.f, 0.f, 0.f, 0.f);

    // ---- parameter tables (per block, parallel, __sincosf) ----
    if (t < NL * NQ) {
        int L = t / NQ, q = t % NQ;
        float th = w[L * NQ + q];
        float c, s;
        __sincosf(0.5f * th, &s, &c);
        float2 RX[2][2] = {{{c, 0.f}, {0.f, -s}}, {{0.f, -s}, {c, 0.f}}};
        float2 RY[2][2] = {{{c, 0.f}, {-s, 0.f}}, {{s, 0.f}, {c, 0.f}}};
        float2 RZ[2][2] = {{{c, -s}, {0.f, 0.f}}, {{0.f, 0.f}, {c, s}}};
        float2 T[2][2], M[2][2];
        #pragma unroll
        for (int i = 0; i < 2; i++)
            #pragma unroll
            for (int j = 0; j < 2; j++)
                T[i][j] = caddh(cmulh(RY[i][0], RX[0][j]),
                                cmulh(RY[i][1], RX[1][j]));
        #pragma unroll
        for (int i = 0; i < 2; i++)
            #pragma unroll
            for (int j = 0; j < 2; j++)
                M[i][j] = caddh(cmulh(RZ[i][0], T[0][j]),
                                cmulh(RZ[i][1], T[1][j]));
        if (L > 0) {  // fold previous layer's RX(beta): M_eff = M * RXb
            float cb, sb;
            __sincosf(0.5f * bet[L - 1], &sb, &cb);
            float2 RXb[2][2] = {{{cb, 0.f}, {0.f, -sb}},
                                {{0.f, -sb}, {cb, 0.f}}};
            float2 E[2][2];
            #pragma unroll
            for (int i = 0; i < 2; i++)
                #pragma unroll
                for (int j = 0; j < 2; j++)
                    E[i][j] = caddh(cmulh(M[i][0], RXb[0][j]),
                                    cmulh(M[i][1], RXb[1][j]));
            #pragma unroll
            for (int i = 0; i < 2; i++)
                #pragma unroll
                for (int j = 0; j < 2; j++)
                    M[i][j] = E[i][j];
        }
        #pragma unroll
        for (int i = 0; i < 2; i++)
            #pragma unroll
            for (int j = 0; j < 2; j++)
                ps.U[L][q][i][j] = M[i][j];
        __sincosf(0.5f * ew[L * NQ + q], &ps.se[L][q], &ps.ce[L][q]);
    }
    if (t >= 16 && t < 16 + NL * 16) {
        int r = t - 16;
        int L = r / 16, idx = r % 16;
        int k = 0;
        #pragma unroll
        for (int i = 0; i < 3; i++) {
            int bi = (idx >> (3 - i)) & 1;
            int bj = (idx >> (2 - i)) & 1;
            if (bi == bj) k++;
        }
        float ang = 0.5f * gam[L] * (float)(3 - 2 * k);
        float sa, ca;
        __sincosf(ang, &sa, &ca);
        ps.dg[L][idx] = make_float2(ca, sa);
    }
    if (t == 64) {
        float cb, sb;
        __sincosf(bet[NL - 1], &sb, &cb);  // FULL angle
        mbsh = make_float2(cb, sb);
    }
    __syncthreads();

    // ---- warp-shuffle basis evolution: all 8 warps, 2 columns each ----
    {
        int lane = t & 31;
        int i = lane & 15;                       // amplitude index
        int col = ((t >> 5) << 1) | (lane >> 4); // basis column 0..15
        float ax = (i == col) ? 1.f : 0.f;
        float ay = 0.f;

        #pragma unroll
        for (int L = 0; L < NL; L++) {
            // combined single-qubit U per qubit (butterfly over mask)
            #pragma unroll
            for (int q = 0; q < NQ; q++) {
                int m = 8 >> q;
                float2 u00 = ps.U[L][q][0][0], u01 = ps.U[L][q][0][1];
                float2 u10 = ps.U[L][q][1][0], u11 = ps.U[L][q][1][1];
                bool bit = (i & m) != 0;
                // self coeff: bit? u11 : u00 ; partner coeff: bit? u10 : u01
                float csx = bit ? u11.x : u00.x, csy = bit ? u11.y : u00.y;
                float cpx = bit ? u10.x : u01.x, cpy = bit ? u10.y : u01.y;
                float px = __shfl_xor_sync(0xffffffffu, ax, m);
                float py = __shfl_xor_sync(0xffffffffu, ay, m);
                float nr = csx * ax;
                nr = fmaf(-csy, ay, nr);
                nr = fmaf(cpx, px, nr);
                nr = fmaf(-cpy, py, nr);
                float ni = csx * ay;
                ni = fmaf(csy, ax, ni);
                ni = fmaf(cpx, py, ni);
                ni = fmaf(cpy, px, ni);
                ax = nr; ay = ni;
            }
            // cRX ring: control q, target (q+1)%4 (RX symmetric -> uniform)
            #pragma unroll
            for (int q = 0; q < NQ; q++) {
                int cm = 8 >> q;
                int tm = 8 >> ((q + 1) & 3);
                float c = ps.ce[L][q], s = ps.se[L][q];
                bool on = (i & cm) != 0;
                float ce_ = on ? c : 1.f;
                float se_ = on ? s : 0.f;
                float px = __shfl_xor_sync(0xffffffffu, ax, tm);
                float py = __shfl_xor_sync(0xffffffffu, ay, tm);
                float nr = fmaf(ce_, ax, se_ * py);
                float ni = fmaf(ce_, ay, -se_ * px);
                ax = nr; ay = ni;
            }
            // diffuser: psi_i -= (psi9+psi11+psi13+psi15)/2, i in {9,11,13,15}
            {
                bool sel = ((i & 9) == 9);
                float h = sel ? 0.5f : 0.f;
                float vx = sel ? ax : 0.f;
                float vy = sel ? ay : 0.f;
                vx += __shfl_xor_sync(0xffffffffu, vx, 2);
                vy += __shfl_xor_sync(0xffffffffu, vy, 2);
                vx += __shfl_xor_sync(0xffffffffu, vx, 4);
                vy += __shfl_xor_sync(0xffffffffu, vy, 4);
                ax = fmaf(-h, vx, ax);
                ay = fmaf(-h, vy, ay);
            }
            // RZZ diagonal phase
            {
                float2 ph = ps.dg[L][i];
                float nr = ph.x * ax; nr = fmaf(-ph.y, ay, nr);
                float ni = ph.x * ay; ni = fmaf(ph.y, ax, ni);
                ax = nr; ay = ni;
            }
        }
        Wsh[i][col] = make_float2(ax, ay);
    }
    __syncthreads();

    if (!act) return;

    // ---- encode: p = tensor_q (cos x_q/2, sin x_q/2), real ----
    float p[16];
    {
        float cq[4], sq[4];
        __sincosf(0.5f * xv.x, &sq[0], &cq[0]);
        __sincosf(0.5f * xv.y, &sq[1], &cq[1]);
        __sincosf(0.5f * xv.z, &sq[2], &cq[2]);
        __sincosf(0.5f * xv.w, &sq[3], &cq[3]);
        float a01[4], a012[8];
        a01[0] = cq[0] * cq[1]; a01[1] = cq[0] * sq[1];
        a01[2] = sq[0] * cq[1]; a01[3] = sq[0] * sq[1];
        #pragma unroll
        for (int k = 0; k < 4; k++) {
            a012[2 * k]     = a01[k] * cq[2];
            a012[2 * k + 1] = a01[k] * sq[2];
        }
        #pragma unroll
        for (int m = 0; m < 8; m++) {
            p[2 * m]     = a012[m] * cq[3];
            p[2 * m + 1] = a012[m] * sq[3];
        }
    }

    // ---- psi = W @ p (complex x real matvec, 512 FMA) ----
    float2 psi[16];
    #pragma unroll
    for (int i = 0; i < 16; i++) {
        const float4* row = reinterpret_cast<const float4*>(&Wsh[i][0]);
        float re = 0.f, im = 0.f;
        #pragma unroll
        for (int jj = 0; jj < 8; jj++) {
            float4 v = row[jj];  // (W[i][2jj].re,.im, W[i][2jj+1].re,.im)
            re = fmaf(v.x, p[2 * jj], re);
            im = fmaf(v.y, p[2 * jj], im);
            re = fmaf(v.z, p[2 * jj + 1], re);
            im = fmaf(v.w, p[2 * jj + 1], im);
        }
        psi[i] = make_float2(re, im);
    }

    // ---- measurement with RX(beta2) fold; T == 1 by unitarity ----
    float cb = mbsh.x, sb = mbsh.y;

    float sq2[16];
    #pragma unroll
    for (int i = 0; i < 16; i++)
        sq2[i] = fmaf(psi[i].x, psi[i].x, psi[i].y * psi[i].y);

    float res[12];
    #pragma unroll
    for (int q = 0; q < NQ; q++) {
        int mask = 8 >> q;
        float s1 = 0.f;
        #pragma unroll
        for (int i = 0; i < 16; i++)
            if (i & mask) s1 += sq2[i];
        float z = fmaf(-2.f, s1, 1.f);

        float xr = 0.f, yi = 0.f;
        #pragma unroll
        for (int i = 0; i < 16; i++) {
            if (i & mask) continue;
            int j = i | mask;
            float2 a = psi[i], d = psi[j];
            xr = fmaf(a.x, d.x, xr); xr = fmaf(a.y, d.y, xr);   // Re(conj(a)d)
            yi = fmaf(a.x, d.y, yi); yi = fmaf(-a.y, d.x, yi);  // Im(conj(a)d)
        }
        float xo = 2.f * xr, yo = 2.f * yi;
        res[q]     = fmaf(cb, z, sb * yo);      // z' = cb*z + sb*y
        res[4 + q] = xo;                        // x' = x
        res[8 + q] = fmaf(cb, yo, -sb * z);     // y' = cb*y - sb*z
    }

    float4* o = reinterpret_cast<float4*>(out + (size_t)b * 12);
    o[0] = make_float4(res[0], res[1], res[2],  res[3]);
    o[1] = make_float4(res[4], res[5], res[6],  res[7]);
    o[2] = make_float4(res[8], res[9], res[10], res[11]);
}

extern "C" void kernel_launch(void* const* d_in, const int* in_sizes, int n_in,
                              void* d_out, int out_size) {
    const float* x   = (const float*)d_in[0];  // (B, 4)
    const float* w   = (const float*)d_in[1];  // (3, 4)
    const float* ew  = (const float*)d_in[2];  // (3, 4)
    const float* gam = (const float*)d_in[3];  // (3,)
    const float* bet = (const float*)d_in[4];  // (3,)
    float* out = (float*)d_out;                // (B, 12)

    int n = in_sizes[0] / 4;

    int threads = 256;
    int blocks = (n + threads - 1) / threads;
    vqc_kernel<<<blocks, threads>>>((const float4*)x, out, w, ew, gam, bet, n);
}

// round 14
// speedup vs baseline: 1.2183x; 1.1218x over previous
#include <cuda_runtime.h>

// QnnFormerVQC round 14: SINGLE kernel, grid-stride x4.
//  - Each block (256 threads) handles 4 consecutive 256-element chunks, so
//    the per-block redundant W evolution (warp-shuffle butterflies) is
//    amortized 4x. All 4 input float4s are prefetched before the evolution
//    chain (MLP=4 hides GMEM latency behind it).
//  - Evolution: all 8 warps, one amplitude per lane (i = lane&15), column =
//    2*warp + lane/16; gate pairs exchange via __shfl_xor_sync -> Wsh[16][16].
//  - Body per chunk (verified): p = real encoding tensor; psi = W @ p
//    (512 FMA); measurement with RX(beta2) folded in (z'=cb*z+sb*y,
//    y'=cb*y-sb*z, x'=x; T==1 by unitarity).
// Circuit reductions (verified vs round-3 literal oracle):
//  - RZ*RY*RX(w) -> one 2x2 matrix U per (L,q); RX(beta0/1) folded into the
//    next layer's U. Reference's _apmcx == swap amplitudes 7<->15, so the
//    H/X/MCX block == psi_i -= sum(psi9,11,13,15)/2 on {9,11,13,15}.
//  - CX-RZ(gamma)-CX chain == 16-entry diagonal phase table.
// Bit convention: qubit q <-> mask (8 >> q), qubit 0 = MSB.

#define NQ 4
#define NL 3
#define CHUNKS 4

struct PS {
    float2 U[NL][NQ][2][2];
    float  ce[NL][NQ], se[NL][NQ];
    float2 dg[NL][16];
};

__device__ __forceinline__ float2 cmulh(float2 a, float2 b) {
    return make_float2(a.x * b.x - a.y * b.y, a.x * b.y + a.y * b.x);
}
__device__ __forceinline__ float2 caddh(float2 a, float2 b) {
    return make_float2(a.x + b.x, a.y + b.y);
}

__global__ void __launch_bounds__(256)
vqc_kernel(const float4* __restrict__ x,
           float* __restrict__ out,
           const float* __restrict__ w,
           const float* __restrict__ ew,
           const float* __restrict__ gam,
           const float* __restrict__ bet,
           int n) {
    __shared__ PS ps;
    __shared__ float2 Wsh[16][16];
    __shared__ float2 mbsh;

    int t = threadIdx.x;
    int base = blockIdx.x * (256 * CHUNKS) + t;

    // ---- prefetch all inputs (MLP=CHUNKS; hidden behind evolution) ----
    float4 xv[CHUNKS];
    bool act[CHUNKS];
    #pragma unroll
    for (int c = 0; c < CHUNKS; c++) {
        int e = base + c * 256;
        act[c] = (e < n);
        xv[c] = act[c] ? x[e] : make_float4(0.f, 0.f, 0.f, 0.f);
    }

    // ---- parameter tables (per block, parallel, __sincosf) ----
    if (t < NL * NQ) {
        int L = t / NQ, q = t % NQ;
        float th = w[L * NQ + q];
        float c, s;
        __sincosf(0.5f * th, &s, &c);
        float2 RX[2][2] = {{{c, 0.f}, {0.f, -s}}, {{0.f, -s}, {c, 0.f}}};
        float2 RY[2][2] = {{{c, 0.f}, {-s, 0.f}}, {{s, 0.f}, {c, 0.f}}};
        float2 RZ[2][2] = {{{c, -s}, {0.f, 0.f}}, {{0.f, 0.f}, {c, s}}};
        float2 T[2][2], M[2][2];
        #pragma unroll
        for (int i = 0; i < 2; i++)
            #pragma unroll
            for (int j = 0; j < 2; j++)
                T[i][j] = caddh(cmulh(RY[i][0], RX[0][j]),
                                cmulh(RY[i][1], RX[1][j]));
        #pragma unroll
        for (int i = 0; i < 2; i++)
            #pragma unroll
            for (int j = 0; j < 2; j++)
                M[i][j] = caddh(cmulh(RZ[i][0], T[0][j]),
                                cmulh(RZ[i][1], T[1][j]));
        if (L > 0) {  // fold previous layer's RX(beta): M_eff = M * RXb
            float cb, sb;
            __sincosf(0.5f * bet[L - 1], &sb, &cb);
            float2 RXb[2][2] = {{{cb, 0.f}, {0.f, -sb}},
                                {{0.f, -sb}, {cb, 0.f}}};
            float2 E[2][2];
            #pragma unroll
            for (int i = 0; i < 2; i++)
                #pragma unroll
                for (int j = 0; j < 2; j++)
                    E[i][j] = caddh(cmulh(M[i][0], RXb[0][j]),
                                    cmulh(M[i][1], RXb[1][j]));
            #pragma unroll
            for (int i = 0; i < 2; i++)
                #pragma unroll
                for (int j = 0; j < 2; j++)
                    M[i][j] = E[i][j];
        }
        #pragma unroll
        for (int i = 0; i < 2; i++)
            #pragma unroll
            for (int j = 0; j < 2; j++)
                ps.U[L][q][i][j] = M[i][j];
        __sincosf(0.5f * ew[L * NQ + q], &ps.se[L][q], &ps.ce[L][q]);
    }
    if (t >= 16 && t < 16 + NL * 16) {
        int r = t - 16;
        int L = r / 16, idx = r % 16;
        int k = 0;
        #pragma unroll
        for (int i = 0; i < 3; i++) {
            int bi = (idx >> (3 - i)) & 1;
            int bj = (idx >> (2 - i)) & 1;
            if (bi == bj) k++;
        }
        float ang = 0.5f * gam[L] * (float)(3 - 2 * k);
        float sa, ca;
        __sincosf(ang, &sa, &ca);
        ps.dg[L][idx] = make_float2(ca, sa);
    }
    if (t == 64) {
        float cb, sb;
        __sincosf(bet[NL - 1], &sb, &cb);  // FULL angle
        mbsh = make_float2(cb, sb);
    }
    __syncthreads();

    // ---- warp-shuffle basis evolution: all 8 warps, 2 columns each ----
    {
        int lane = t & 31;
        int i = lane & 15;                       // amplitude index
        int col = ((t >> 5) << 1) | (lane >> 4); // basis column 0..15
        float ax = (i == col) ? 1.f : 0.f;
        float ay = 0.f;

        #pragma unroll
        for (int L = 0; L < NL; L++) {
            // combined single-qubit U per qubit (butterfly over mask)
            #pragma unroll
            for (int q = 0; q < NQ; q++) {
                int m = 8 >> q;
                float2 u00 = ps.U[L][q][0][0], u01 = ps.U[L][q][0][1];
                float2 u10 = ps.U[L][q][1][0], u11 = ps.U[L][q][1][1];
                bool bit = (i & m) != 0;
                float csx = bit ? u11.x : u00.x, csy = bit ? u11.y : u00.y;
                float cpx = bit ? u10.x : u01.x, cpy = bit ? u10.y : u01.y;
                float px = __shfl_xor_sync(0xffffffffu, ax, m);
                float py = __shfl_xor_sync(0xffffffffu, ay, m);
                float nr = csx * ax;
                nr = fmaf(-csy, ay, nr);
                nr = fmaf(cpx, px, nr);
                nr = fmaf(-cpy, py, nr);
                float ni = csx * ay;
                ni = fmaf(csy, ax, ni);
                ni = fmaf(cpx, py, ni);
                ni = fmaf(cpy, px, ni);
                ax = nr; ay = ni;
            }
            // cRX ring: control q, target (q+1)%4 (RX symmetric -> uniform)
            #pragma unroll
            for (int q = 0; q < NQ; q++) {
                int cm = 8 >> q;
                int tm = 8 >> ((q + 1) & 3);
                float c = ps.ce[L][q], s = ps.se[L][q];
                bool on = (i & cm) != 0;
                float ce_ = on ? c : 1.f;
                float se_ = on ? s : 0.f;
                float px = __shfl_xor_sync(0xffffffffu, ax, tm);
                float py = __shfl_xor_sync(0xffffffffu, ay, tm);
                float nr = fmaf(ce_, ax, se_ * py);
                float ni = fmaf(ce_, ay, -se_ * px);
                ax = nr; ay = ni;
            }
            // diffuser: psi_i -= (psi9+psi11+psi13+psi15)/2, i in {9,11,13,15}
            {
                bool sel = ((i & 9) == 9);
                float h = sel ? 0.5f : 0.f;
                float vx = sel ? ax : 0.f;
                float vy = sel ? ay : 0.f;
                vx += __shfl_xor_sync(0xffffffffu, vx, 2);
                vy += __shfl_xor_sync(0xffffffffu, vy, 2);
                vx += __shfl_xor_sync(0xffffffffu, vx, 4);
                vy += __shfl_xor_sync(0xffffffffu, vy, 4);
                ax = fmaf(-h, vx, ax);
                ay = fmaf(-h, vy, ay);
            }
            // RZZ diagonal phase
            {
                float2 ph = ps.dg[L][i];
                float nr = ph.x * ax; nr = fmaf(-ph.y, ay, nr);
                float ni = ph.x * ay; ni = fmaf(ph.y, ax, ni);
                ax = nr; ay = ni;
            }
        }
        Wsh[i][col] = make_float2(ax, ay);
    }
    __syncthreads();

    float cb = mbsh.x, sb = mbsh.y;

    // ---- body: 4 chunks per block ----
    #pragma unroll
    for (int c = 0; c < CHUNKS; c++) {
        if (!act[c]) continue;

        // encode: p = tensor_q (cos x_q/2, sin x_q/2), real
        float p[16];
        {
            float cq[4], sq[4];
            __sincosf(0.5f * xv[c].x, &sq[0], &cq[0]);
            __sincosf(0.5f * xv[c].y, &sq[1], &cq[1]);
            __sincosf(0.5f * xv[c].z, &sq[2], &cq[2]);
            __sincosf(0.5f * xv[c].w, &sq[3], &cq[3]);
            float a01[4], a012[8];
            a01[0] = cq[0] * cq[1]; a01[1] = cq[0] * sq[1];
            a01[2] = sq[0] * cq[1]; a01[3] = sq[0] * sq[1];
            #pragma unroll
            for (int k = 0; k < 4; k++) {
                a012[2 * k]     = a01[k] * cq[2];
                a012[2 * k + 1] = a01[k] * sq[2];
            }
            #pragma unroll
            for (int m = 0; m < 8; m++) {
                p[2 * m]     = a012[m] * cq[3];
                p[2 * m + 1] = a012[m] * sq[3];
            }
        }

        // psi = W @ p (complex x real matvec, 512 FMA)
        float2 psi[16];
        #pragma unroll
        for (int i = 0; i < 16; i++) {
            const float4* row = reinterpret_cast<const float4*>(&Wsh[i][0]);
            float re = 0.f, im = 0.f;
            #pragma unroll
            for (int jj = 0; jj < 8; jj++) {
                float4 v = row[jj];  // (W[i][2jj].re,.im, W[i][2jj+1].re,.im)
                re = fmaf(v.x, p[2 * jj], re);
                im = fmaf(v.y, p[2 * jj], im);
                re = fmaf(v.z, p[2 * jj + 1], re);
                im = fmaf(v.w, p[2 * jj + 1], im);
            }
            psi[i] = make_float2(re, im);
        }

        // measurement with RX(beta2) fold; T == 1 by unitarity
        float sq2[16];
        #pragma unroll
        for (int i = 0; i < 16; i++)
            sq2[i] = fmaf(psi[i].x, psi[i].x, psi[i].y * psi[i].y);

        float res[12];
        #pragma unroll
        for (int q = 0; q < NQ; q++) {
            int mask = 8 >> q;
            float s1 = 0.f;
            #pragma unroll
            for (int i = 0; i < 16; i++)
                if (i & mask) s1 += sq2[i];
            float z = fmaf(-2.f, s1, 1.f);

            float xr = 0.f, yi = 0.f;
            #pragma unroll
            for (int i = 0; i < 16; i++) {
                if (i & mask) continue;
                int j = i | mask;
                float2 a = psi[i], d = psi[j];
                xr = fmaf(a.x, d.x, xr); xr = fmaf(a.y, d.y, xr);
                yi = fmaf(a.x, d.y, yi); yi = fmaf(-a.y, d.x, yi);
            }
            float xo = 2.f * xr, yo = 2.f * yi;
            res[q]     = fmaf(cb, z, sb * yo);      // z' = cb*z + sb*y
            res[4 + q] = xo;                        // x' = x
            res[8 + q] = fmaf(cb, yo, -sb * z);     // y' = cb*y - sb*z
        }

        int e = base + c * 256;
        float4* o = reinterpret_cast<float4*>(out + (size_t)e * 12);
        o[0] = make_float4(res[0], res[1], res[2],  res[3]);
        o[1] = make_float4(res[4], res[5], res[6],  res[7]);
        o[2] = make_float4(res[8], res[9], res[10], res[11]);
    }
}

extern "C" void kernel_launch(void* const* d_in, const int* in_sizes, int n_in,
                              void* d_out, int out_size) {
    const float* x   = (const float*)d_in[0];  // (B, 4)
    const float* w   = (const float*)d_in[1];  // (3, 4)
    const float* ew  = (const float*)d_in[2];  // (3, 4)
    const float* gam = (const float*)d_in[3];  // (3,)
    const float* bet = (const float*)d_in[4];  // (3,)
    float* out = (float*)d_out;                // (B, 12)

    int n = in_sizes[0] / 4;

    int threads = 256;
    int per_block = threads * CHUNKS;
    int blocks = (n + per_block - 1) / per_block;
    vqc_kernel<<<blocks, threads>>>((const float4*)x, out, w, ew, gam, bet, n);
}